// round 3
// baseline (speedup 1.0000x reference)
#include <cuda_runtime.h>
#include <cuda_bf16.h>

// TenHotEncodeLayer: out[n, t, x[n,t,f]] = 1.0 for f in [0,10); all else 0.
// x: [32, 512, 10] int32, out: [32, 512, 5000] float32.
//
// Strategy v3: decouple fill and scatter.
//   1) cudaMemsetAsync zeros the whole 327.7 MB output — the driver's memset
//      kernel is a pure grid-stride streaming fill with no per-row overhead;
//      this probes the true DRAM write roofline.
//   2) A tiny scatter kernel writes 1.0f at the 163,840 indexed positions
//      (independent fire-and-forget 4B stores, stream-ordered after memset).

#define NUM_TOKENS 5000
#define NUM_F 10
#define TPB 256

__global__ __launch_bounds__(TPB) void tenhot_scatter_kernel(
    const int* __restrict__ x, float* __restrict__ out, int total)
{
    int i = blockIdx.x * TPB + threadIdx.x;   // i = row * NUM_F + f
    if (i < total) {
        int row = i / NUM_F;
        int c = __ldg(&x[i]);
        out[(size_t)row * NUM_TOKENS + c] = 1.0f;
    }
}

extern "C" void kernel_launch(void* const* d_in, const int* in_sizes, int n_in,
                              void* d_out, int out_size)
{
    const int* x = (const int*)d_in[0];
    float* out = (float*)d_out;
    const int total = in_sizes[0];            // 32*512*10 = 163840

    cudaMemsetAsync(d_out, 0, (size_t)out_size * sizeof(float));
    tenhot_scatter_kernel<<<(total + TPB - 1) / TPB, TPB>>>(x, out, total);
}

// round 4
// speedup vs baseline: 1.2007x; 1.2007x over previous
#include <cuda_runtime.h>
#include <cuda_bf16.h>

// TenHotEncodeLayer: out[n, t, x[n,t,f]] = 1.0 for f in [0,10); all else 0.
// x: [32, 512, 10] int32, out: [32, 512, 5000] float32.
//
// Strategy v4 (refinement of winning v1):
//   - 2 rows per CTA (8192 CTAs): halves per-CTA overhead (index loads,
//     __syncthreads, wave tails) and gives each thread 10 back-to-back
//     STG.128 for deeper store MLP.
//   - __stcs (evict-first streaming) on the zero fill: the 327 MB write
//     stream is never re-read, so don't let it fight for L2 residency.
//   - Fused patch: 20 threads overwrite the indexed positions with 1.0
//     after a block barrier (lines still L2-hot).

#define NUM_TOKENS 5000
#define NUM_F 10
#define TPB 256
#define ROWS_PER_CTA 2
#define CTA_F4 (NUM_TOKENS * ROWS_PER_CTA / 4)   // 2500
#define FULL_CHUNKS (CTA_F4 / TPB)               // 9
#define TAIL (CTA_F4 - FULL_CHUNKS * TPB)        // 196

__global__ __launch_bounds__(TPB) void tenhot_kernel(
    const int* __restrict__ x, float4* __restrict__ out)
{
    const int row0 = blockIdx.x * ROWS_PER_CTA;
    const int tid  = threadIdx.x;

    // Prefetch this thread's scatter index early (hidden under the fill).
    int c = 0;
    if (tid < NUM_F * ROWS_PER_CTA) c = __ldg(&x[row0 * NUM_F + tid]);

    float4* o = out + (size_t)row0 * (NUM_TOKENS / 4);
    const float4 z = make_float4(0.f, 0.f, 0.f, 0.f);

    // 2500 = 9*256 + 196: 9 unconditional + 1 predicated streaming store.
#pragma unroll
    for (int k = 0; k < FULL_CHUNKS; k++)
        __stcs(&o[tid + TPB * k], z);
    if (tid < TAIL)
        __stcs(&o[tid + TPB * FULL_CHUNKS], z);

    __syncthreads();

    if (tid < NUM_F * ROWS_PER_CTA) {
        // local row = tid / NUM_F, column = c
        float* of = reinterpret_cast<float*>(o) + (tid / NUM_F) * NUM_TOKENS;
        of[c] = 1.0f;
    }
}

extern "C" void kernel_launch(void* const* d_in, const int* in_sizes, int n_in,
                              void* d_out, int out_size)
{
    const int* x = (const int*)d_in[0];
    float4* out = (float4*)d_out;
    const int rows = in_sizes[0] / NUM_F;        // 16384
    tenhot_kernel<<<rows / ROWS_PER_CTA, TPB>>>(x, out);
}